// round 1
// baseline (speedup 1.0000x reference)
#include <cuda_runtime.h>
#include <cuda_bf16.h>
#include <math.h>

// Problem constants
#define BATCH 4
#define NTOK  2048
#define FEATS 1024
#define NHEAD 16
#define HDIM  64
#define MROWS (BATCH * NTOK)   // 8192

// ---------------- scratch (device globals: allocation-free) ----------------
__device__ float g_q[MROWS * FEATS];
__device__ float g_k[MROWS * FEATS];
__device__ float g_v[MROWS * FEATS];
__device__ float g_a[MROWS * FEATS];
__device__ float g_S[BATCH * NHEAD * HDIM * HDIM];

// ---------------- SGEMM: C = A[MxK] @ B[KxN] + bias[N] ----------------
#define BM 128
#define BN_ 128
#define BK 8
#define TM 8
#define TN 8

__global__ __launch_bounds__(256) void sgemm_bias_kernel(
    const float* __restrict__ A, const float* __restrict__ B,
    const float* __restrict__ bias, float* __restrict__ C,
    int M, int N, int K)
{
    __shared__ float As[BK][BM];
    __shared__ float Bs[BK][BN_];

    const int tid = threadIdx.x;
    const int bx = blockIdx.x;   // N tile
    const int by = blockIdx.y;   // M tile

    const float* Ablk = A + (size_t)by * BM * K;
    const float* Bblk = B + (size_t)bx * BN_;

    // A tile loads: 128x8 floats, one float4 per thread
    const int arow = tid >> 1;           // 0..127
    const int acol = (tid & 1) * 4;      // 0 or 4
    // B tile loads: 8x128 floats, one float4 per thread
    const int brow = tid >> 5;           // 0..7
    const int bcol = (tid & 31) * 4;     // 0..124

    const int tx = tid & 15;             // 0..15 -> N
    const int ty = tid >> 4;             // 0..15 -> M

    float acc[TM][TN];
    #pragma unroll
    for (int i = 0; i < TM; i++)
        #pragma unroll
        for (int j = 0; j < TN; j++) acc[i][j] = 0.f;

    for (int k0 = 0; k0 < K; k0 += BK) {
        float4 av = *(const float4*)(Ablk + (size_t)arow * K + k0 + acol);
        As[acol + 0][arow] = av.x;
        As[acol + 1][arow] = av.y;
        As[acol + 2][arow] = av.z;
        As[acol + 3][arow] = av.w;
        float4 bv = *(const float4*)(Bblk + (size_t)(k0 + brow) * N + bcol);
        *(float4*)(&Bs[brow][bcol]) = bv;
        __syncthreads();

        #pragma unroll
        for (int kk = 0; kk < BK; kk++) {
            float ra[TM], rb[TN];
            float4 a0 = *(const float4*)(&As[kk][ty * TM]);
            float4 a1 = *(const float4*)(&As[kk][ty * TM + 4]);
            ra[0]=a0.x; ra[1]=a0.y; ra[2]=a0.z; ra[3]=a0.w;
            ra[4]=a1.x; ra[5]=a1.y; ra[6]=a1.z; ra[7]=a1.w;
            float4 b0 = *(const float4*)(&Bs[kk][tx * TN]);
            float4 b1 = *(const float4*)(&Bs[kk][tx * TN + 4]);
            rb[0]=b0.x; rb[1]=b0.y; rb[2]=b0.z; rb[3]=b0.w;
            rb[4]=b1.x; rb[5]=b1.y; rb[6]=b1.z; rb[7]=b1.w;
            #pragma unroll
            for (int i = 0; i < TM; i++)
                #pragma unroll
                for (int j = 0; j < TN; j++)
                    acc[i][j] = fmaf(ra[i], rb[j], acc[i][j]);
        }
        __syncthreads();
    }

    float* Cblk = C + (size_t)by * BM * N + (size_t)bx * BN_;
    #pragma unroll
    for (int i = 0; i < TM; i++) {
        int row = ty * TM + i;
        #pragma unroll
        for (int j = 0; j < TN; j += 4) {
            int col = tx * TN + j;
            float4 o;
            o.x = acc[i][j + 0] + bias[bx * BN_ + col + 0];
            o.y = acc[i][j + 1] + bias[bx * BN_ + col + 1];
            o.z = acc[i][j + 2] + bias[bx * BN_ + col + 2];
            o.w = acc[i][j + 3] + bias[bx * BN_ + col + 3];
            *(float4*)(Cblk + (size_t)row * N + col) = o;
        }
    }
}

// ---------------- L2 normalize per (token, head) over HDIM=64 ----------------
// one warp per row; lane handles elements lane and lane+32
__global__ __launch_bounds__(256) void l2norm_kernel(float* __restrict__ p, int nrows)
{
    int warp = (blockIdx.x * blockDim.x + threadIdx.x) >> 5;
    int lane = threadIdx.x & 31;
    if (warp >= nrows) return;
    // row -> (bn, h): base offset = bn*FEATS + h*HDIM, contiguous 64 floats
    int bn = warp >> 4;
    int h  = warp & 15;
    float* base = p + (size_t)bn * FEATS + h * HDIM;
    float v0 = base[lane];
    float v1 = base[lane + 32];
    float ss = v0 * v0 + v1 * v1;
    #pragma unroll
    for (int off = 16; off > 0; off >>= 1)
        ss += __shfl_xor_sync(0xFFFFFFFFu, ss, off);
    float nrm = sqrtf(ss);
    float inv = 1.f / fmaxf(nrm, 1e-12f);
    base[lane]      = v0 * inv;
    base[lane + 32] = v1 * inv;
}

// ---------------- S[bh] = (K^T V)/scale per (b,h): 64x64 ----------------
__global__ __launch_bounds__(256) void ktv_kernel(
    const float* __restrict__ k, const float* __restrict__ v,
    const float* __restrict__ m, float* __restrict__ S)
{
    int bh = blockIdx.x;          // 0..63
    int b = bh >> 4, h = bh & 15;
    const float* kb = k + (size_t)b * NTOK * FEATS + h * HDIM;
    const float* vb = v + (size_t)b * NTOK * FEATS + h * HDIM;

    __shared__ float ks[32][HDIM];
    __shared__ float vs[32][HDIM];

    int tid = threadIdx.x;        // 256
    int p  = tid >> 2;            // 0..63 (row of S)
    int qb = (tid & 3) * 16;      // col base

    float acc[16];
    #pragma unroll
    for (int i = 0; i < 16; i++) acc[i] = 0.f;

    for (int j0 = 0; j0 < NTOK; j0 += 32) {
        #pragma unroll
        for (int i = tid; i < 32 * HDIM; i += 256) {
            int r = i >> 6, c = i & 63;
            ks[r][c] = kb[(size_t)(j0 + r) * FEATS + c];
            vs[r][c] = vb[(size_t)(j0 + r) * FEATS + c];
        }
        __syncthreads();
        #pragma unroll 4
        for (int j = 0; j < 32; j++) {
            float kp = ks[j][p];
            #pragma unroll
            for (int i = 0; i < 16; i++)
                acc[i] = fmaf(kp, vs[j][qb + i], acc[i]);
        }
        __syncthreads();
    }

    float sig = 1.f / (1.f + expf(-m[h]));
    float scale = powf((float)NTOK, sig);
    float inv = 1.f / scale;
    float* Sb = S + (size_t)bh * HDIM * HDIM;
    #pragma unroll
    for (int i = 0; i < 16; i++)
        Sb[p * HDIM + qb + i] = acc[i] * inv;
}

// ---------------- attn_out = Q @ S per (b,h): [2048x64]@[64x64] ----------------
// block: 64 rows x 64 cols; grid (NTOK/64, B*H)
__global__ __launch_bounds__(256) void qs_kernel(
    const float* __restrict__ q, const float* __restrict__ S,
    float* __restrict__ out)
{
    int bh = blockIdx.y;
    int b = bh >> 4, h = bh & 15;
    int row0 = blockIdx.x * 64;

    __shared__ float Ss[HDIM][HDIM];        // 16 KB
    __shared__ float qsm[64][HDIM + 1];     // ~16.6 KB

    const float* qb = q + (size_t)b * NTOK * FEATS + h * HDIM;
    const float* Sb = S + (size_t)bh * HDIM * HDIM;
    float* ob = out + (size_t)b * NTOK * FEATS + h * HDIM;

    int tid = threadIdx.x;
    #pragma unroll
    for (int i = tid; i < 64 * 64; i += 256) {
        int r = i >> 6, c = i & 63;
        Ss[r][c] = Sb[i];
        qsm[r][c] = qb[(size_t)(row0 + r) * FEATS + c];
    }
    __syncthreads();

    int c  = tid & 63;
    int r0 = tid >> 6;    // 0..3
    #pragma unroll
    for (int i = 0; i < 16; i++) {
        int r = i * 4 + r0;
        float acc = 0.f;
        #pragma unroll
        for (int pp = 0; pp < HDIM; pp++)
            acc = fmaf(qsm[r][pp], Ss[pp][c], acc);
        ob[(size_t)(row0 + r) * FEATS + c] = acc;
    }
}

// ---------------- launch ----------------
extern "C" void kernel_launch(void* const* d_in, const int* in_sizes, int n_in,
                              void* d_out, int out_size)
{
    const float* x  = (const float*)d_in[0];
    const float* Wq = (const float*)d_in[1];
    const float* bq = (const float*)d_in[2];
    const float* Wk = (const float*)d_in[3];
    const float* bk = (const float*)d_in[4];
    const float* Wv = (const float*)d_in[5];
    const float* bv = (const float*)d_in[6];
    const float* Wo = (const float*)d_in[7];
    const float* bo = (const float*)d_in[8];
    const float* m  = (const float*)d_in[9];
    float* out = (float*)d_out;

    float *q, *k, *v, *a, *S;
    cudaGetSymbolAddress((void**)&q, g_q);
    cudaGetSymbolAddress((void**)&k, g_k);
    cudaGetSymbolAddress((void**)&v, g_v);
    cudaGetSymbolAddress((void**)&a, g_a);
    cudaGetSymbolAddress((void**)&S, g_S);

    dim3 gemm_grid(FEATS / BN_, MROWS / BM);   // (8, 64)
    sgemm_bias_kernel<<<gemm_grid, 256>>>(x, Wq, bq, q, MROWS, FEATS, FEATS);
    sgemm_bias_kernel<<<gemm_grid, 256>>>(x, Wk, bk, k, MROWS, FEATS, FEATS);
    sgemm_bias_kernel<<<gemm_grid, 256>>>(x, Wv, bv, v, MROWS, FEATS, FEATS);

    int nrows = MROWS * NHEAD;                  // 131072
    int l2blocks = nrows / 8;                   // 8 warps per block
    l2norm_kernel<<<l2blocks, 256>>>(q, nrows);
    l2norm_kernel<<<l2blocks, 256>>>(k, nrows);

    ktv_kernel<<<BATCH * NHEAD, 256>>>(k, v, m, S);

    dim3 qs_grid(NTOK / 64, BATCH * NHEAD);     // (32, 64)
    qs_kernel<<<qs_grid, 256>>>(q, S, a);

    sgemm_bias_kernel<<<gemm_grid, 256>>>(a, Wo, bo, out, MROWS, FEATS, FEATS);
}

// round 2
// speedup vs baseline: 2.3441x; 2.3441x over previous
#include <cuda_runtime.h>
#include <cuda_bf16.h>
#include <math.h>
#include <stdint.h>

// Problem constants
#define BATCH 4
#define NTOK  2048
#define FEATS 1024
#define NHEAD 16
#define HDIM  64
#define MROWS (BATCH * NTOK)   // 8192
#define KDIM  1024
#define NDIM  1024

// ---------------- scratch (device globals: allocation-free) ----------------
__device__ float g_q[MROWS * FEATS];
__device__ float g_k[MROWS * FEATS];
__device__ float g_v[MROWS * FEATS];
__device__ float g_S[BATCH * NHEAD * HDIM * HDIM];
__device__ float g_Sp[8 * BATCH * NHEAD * HDIM * HDIM];

__device__ __nv_bfloat16 g_xh[MROWS * FEATS];
__device__ __nv_bfloat16 g_xl[MROWS * FEATS];
__device__ __nv_bfloat16 g_ah[MROWS * FEATS];
__device__ __nv_bfloat16 g_al[MROWS * FEATS];
// weights: 0=Wq 1=Wk 2=Wv 3=Wo
__device__ __nv_bfloat16 g_wh[4 * KDIM * NDIM];
__device__ __nv_bfloat16 g_wl[4 * KDIM * NDIM];

// ---------------- split fp32 -> (hi, lo) bf16 ----------------
__device__ __forceinline__ void split2(float v, __nv_bfloat16& h, __nv_bfloat16& l) {
    h = __float2bfloat16(v);
    l = __float2bfloat16(v - __bfloat162float(h));
}

__global__ __launch_bounds__(256) void split_kernel(
    const float* __restrict__ src, __nv_bfloat16* __restrict__ hi,
    __nv_bfloat16* __restrict__ lo, int n4)
{
    int i = blockIdx.x * blockDim.x + threadIdx.x;
    if (i >= n4) return;
    float4 v = ((const float4*)src)[i];
    __nv_bfloat16 h0,h1,h2,h3,l0,l1,l2,l3;
    split2(v.x,h0,l0); split2(v.y,h1,l1); split2(v.z,h2,l2); split2(v.w,h3,l3);
    __nv_bfloat162* hp = (__nv_bfloat162*)hi;
    __nv_bfloat162* lp = (__nv_bfloat162*)lo;
    hp[i*2]   = __nv_bfloat162(h0,h1);
    hp[i*2+1] = __nv_bfloat162(h2,h3);
    lp[i*2]   = __nv_bfloat162(l0,l1);
    lp[i*2+1] = __nv_bfloat162(l2,l3);
}

// ---------------- bf16 split-3 tensor-core GEMM ----------------
// C[8192x1024] = Ah@Bh + Al@Bh + Ah@Bl + bias, fp32 out
#define BM 128
#define BN_ 128
#define BK 32
#define NSTAGE 3
#define KPB (KDIM / BK)          // 32
#define KV_ITERS (3 * KPB)       // 96
#define A_PITCH 40               // bf16 elems, +8 pad
#define B_PITCH 136
#define A_STG_BYTES (BM * A_PITCH * 2)           // 10240
#define B_STG_BYTES (BK * B_PITCH * 2)           // 8704
#define STG_BYTES (A_STG_BYTES + B_STG_BYTES)    // 18944

#define CP_ASYNC16(dst, src) \
    asm volatile("cp.async.cg.shared.global [%0], [%1], 16;\n" :: "r"(dst), "l"(src))
#define CP_COMMIT() asm volatile("cp.async.commit_group;\n")
#define CP_WAIT1()  asm volatile("cp.async.wait_group 1;\n")

#define LDMATRIX_X4(r0,r1,r2,r3,addr) \
    asm volatile("ldmatrix.sync.aligned.m8n8.x4.shared.b16 {%0,%1,%2,%3}, [%4];" \
        : "=r"(r0),"=r"(r1),"=r"(r2),"=r"(r3) : "r"(addr))
#define LDMATRIX_X4_T(r0,r1,r2,r3,addr) \
    asm volatile("ldmatrix.sync.aligned.m8n8.x4.trans.shared.b16 {%0,%1,%2,%3}, [%4];" \
        : "=r"(r0),"=r"(r1),"=r"(r2),"=r"(r3) : "r"(addr))
#define MMA16816(c0,c1,c2,c3,a0,a1,a2,a3,b0,b1) \
    asm volatile("mma.sync.aligned.m16n8k16.row.col.f32.bf16.bf16.f32 " \
        "{%0,%1,%2,%3},{%4,%5,%6,%7},{%8,%9},{%0,%1,%2,%3};" \
        : "+f"(c0),"+f"(c1),"+f"(c2),"+f"(c3) \
        : "r"(a0),"r"(a1),"r"(a2),"r"(a3),"r"(b0),"r"(b1))

__global__ __launch_bounds__(256, 2) void gemm_split3_kernel(
    const __nv_bfloat16* __restrict__ Ah, const __nv_bfloat16* __restrict__ Al,
    const __nv_bfloat16* __restrict__ Bh, const __nv_bfloat16* __restrict__ Bl,
    const float* __restrict__ bias, float* __restrict__ C)
{
    extern __shared__ char dynsmem[];
    const uint32_t sbase = (uint32_t)__cvta_generic_to_shared(dynsmem);

    const int tid = threadIdx.x;
    const int lane = tid & 31;
    const int warp = tid >> 5;
    const int wm = warp & 1;        // 0..1 -> M
    const int wn = warp >> 1;       // 0..3 -> N
    const int blockRow = blockIdx.y * BM;
    const int blockCol = blockIdx.x * BN_;

    // staging smem offsets (stage-relative, bytes)
    const uint32_t aoff0 = (uint32_t)(((tid >> 2) * A_PITCH + (tid & 3) * 8) * 2);
    const uint32_t aoff1 = aoff0 + 64 * A_PITCH * 2;
    const uint32_t boff0 = (uint32_t)(A_STG_BYTES + ((tid >> 4) * B_PITCH + (tid & 15) * 8) * 2);
    const uint32_t boff1 = boff0 + 16 * B_PITCH * 2;
    // gmem element offsets (within the kk-slab)
    const int a_row0 = (tid >> 2), a_cc = (tid & 3) * 8;
    const int b_row0 = (tid >> 4), b_cc = (tid & 15) * 8;

    // ldmatrix lane addressing (stage-relative byte offsets)
    const int a_lrow = wm * 64 + ((lane >> 3) & 1) * 8 + (lane & 7);
    const int a_lcol = (lane >> 4) * 8;
    uint32_t a_base[4];
    #pragma unroll
    for (int i = 0; i < 4; i++)
        a_base[i] = (uint32_t)(((a_lrow + i * 16) * A_PITCH + a_lcol) * 2);

    const int b_lrow = ((lane >> 3) & 1) * 8 + (lane & 7);
    const int b_lcol = (lane >> 4) * 8;
    uint32_t b_base[2];
    #pragma unroll
    for (int jj = 0; jj < 2; jj++)
        b_base[jj] = (uint32_t)(A_STG_BYTES +
            (b_lrow * B_PITCH + wn * 32 + jj * 16 + b_lcol) * 2);

    float c[4][4][4];
    #pragma unroll
    for (int i = 0; i < 4; i++)
        #pragma unroll
        for (int j = 0; j < 4; j++)
            #pragma unroll
            for (int r = 0; r < 4; r++) c[i][j][r] = 0.f;

    // issue one stage of cp.async for virtual iter kv
    auto issue = [&](int kv) {
        int term = kv >> 5;              // /KPB
        int kk = (kv & (KPB - 1)) * BK;
        const __nv_bfloat16* At = (term == 1) ? Al : Ah;
        const __nv_bfloat16* Bt = (term == 2) ? Bl : Bh;
        uint32_t s = sbase + (kv % NSTAGE) * STG_BYTES;
        const __nv_bfloat16* ag = At + (size_t)(blockRow + a_row0) * KDIM + kk + a_cc;
        CP_ASYNC16(s + aoff0, ag);
        CP_ASYNC16(s + aoff1, ag + (size_t)64 * KDIM);
        const __nv_bfloat16* bg = Bt + (size_t)(kk + b_row0) * NDIM + blockCol + b_cc;
        CP_ASYNC16(s + boff0, bg);
        CP_ASYNC16(s + boff1, bg + (size_t)16 * NDIM);
    };

    issue(0); CP_COMMIT();
    issue(1); CP_COMMIT();

    for (int kv = 0; kv < KV_ITERS; kv++) {
        CP_WAIT1();
        __syncthreads();
        uint32_t s = sbase + (kv % NSTAGE) * STG_BYTES;
        #pragma unroll
        for (int ks = 0; ks < 2; ks++) {
            uint32_t ksb = (uint32_t)(ks * 16 * 2);
            uint32_t ksbB = (uint32_t)(ks * 16 * B_PITCH * 2);
            uint32_t a[4][4];
            #pragma unroll
            for (int i = 0; i < 4; i++)
                LDMATRIX_X4(a[i][0], a[i][1], a[i][2], a[i][3], s + a_base[i] + ksb);
            uint32_t b[2][4];
            #pragma unroll
            for (int jj = 0; jj < 2; jj++)
                LDMATRIX_X4_T(b[jj][0], b[jj][1], b[jj][2], b[jj][3], s + b_base[jj] + ksbB);
            #pragma unroll
            for (int i = 0; i < 4; i++)
                #pragma unroll
                for (int j = 0; j < 4; j++)
                    MMA16816(c[i][j][0], c[i][j][1], c[i][j][2], c[i][j][3],
                             a[i][0], a[i][1], a[i][2], a[i][3],
                             b[j >> 1][(j & 1) * 2], b[j >> 1][(j & 1) * 2 + 1]);
        }
        if (kv + 2 < KV_ITERS) issue(kv + 2);
        CP_COMMIT();
    }

    // epilogue
    const int groupID = lane >> 2;
    const int tig = lane & 3;
    #pragma unroll
    for (int i = 0; i < 4; i++) {
        #pragma unroll
        for (int j = 0; j < 4; j++) {
            int row = blockRow + wm * 64 + i * 16 + groupID;
            int col = blockCol + wn * 32 + j * 8 + tig * 2;
            float b0 = bias[col], b1 = bias[col + 1];
            float2 o0 = make_float2(c[i][j][0] + b0, c[i][j][1] + b1);
            float2 o1 = make_float2(c[i][j][2] + b0, c[i][j][3] + b1);
            *(float2*)(C + (size_t)row * NDIM + col) = o0;
            *(float2*)(C + (size_t)(row + 8) * NDIM + col) = o1;
        }
    }
}

// ---------------- L2 normalize per (token, head) over HDIM=64 ----------------
__global__ __launch_bounds__(256) void l2norm_kernel(float* __restrict__ p, int nrows)
{
    int warp = (blockIdx.x * blockDim.x + threadIdx.x) >> 5;
    int lane = threadIdx.x & 31;
    if (warp >= nrows) return;
    int bn = warp >> 4;
    int h  = warp & 15;
    float* base = p + (size_t)bn * FEATS + h * HDIM;
    float v0 = base[lane];
    float v1 = base[lane + 32];
    float ss = v0 * v0 + v1 * v1;
    #pragma unroll
    for (int off = 16; off > 0; off >>= 1)
        ss += __shfl_xor_sync(0xFFFFFFFFu, ss, off);
    float inv = 1.f / fmaxf(sqrtf(ss), 1e-12f);
    base[lane]      = v0 * inv;
    base[lane + 32] = v1 * inv;
}

// ---------------- partial K^T V: per (b,h,chunk of 256 tokens) ----------------
__global__ __launch_bounds__(256) void ktv_partial_kernel(
    const float* __restrict__ k, const float* __restrict__ v,
    float* __restrict__ Sp)
{
    int blk = blockIdx.x;          // 0..511
    int bh = blk >> 3;
    int chunk = blk & 7;
    int b = bh >> 4, h = bh & 15;
    const float* kb = k + (size_t)b * NTOK * FEATS + h * HDIM;
    const float* vb = v + (size_t)b * NTOK * FEATS + h * HDIM;

    __shared__ float ks[32][HDIM];
    __shared__ float vs[32][HDIM];

    int tid = threadIdx.x;
    int p  = tid >> 2;
    int qb = (tid & 3) * 16;

    float acc[16];
    #pragma unroll
    for (int i = 0; i < 16; i++) acc[i] = 0.f;

    int t0 = chunk * 256;
    for (int j0 = t0; j0 < t0 + 256; j0 += 32) {
        #pragma unroll
        for (int i = tid; i < 32 * HDIM; i += 256) {
            int r = i >> 6, cc = i & 63;
            ks[r][cc] = kb[(size_t)(j0 + r) * FEATS + cc];
            vs[r][cc] = vb[(size_t)(j0 + r) * FEATS + cc];
        }
        __syncthreads();
        #pragma unroll 4
        for (int j = 0; j < 32; j++) {
            float kp = ks[j][p];
            #pragma unroll
            for (int i = 0; i < 16; i++)
                acc[i] = fmaf(kp, vs[j][qb + i], acc[i]);
        }
        __syncthreads();
    }
    float* Sb = Sp + ((size_t)bh * 8 + chunk) * HDIM * HDIM;
    #pragma unroll
    for (int i = 0; i < 16; i++)
        Sb[p * HDIM + qb + i] = acc[i];
}

// ---------------- reduce partials + scale ----------------
__global__ __launch_bounds__(256) void ktv_reduce_kernel(
    const float* __restrict__ Sp, const float* __restrict__ m,
    float* __restrict__ S)
{
    int bh = blockIdx.x;
    int h = bh & 15;
    float sig = 1.f / (1.f + expf(-m[h]));
    float inv = 1.f / powf((float)NTOK, sig);
    const float* base = Sp + (size_t)bh * 8 * HDIM * HDIM;
    float* out = S + (size_t)bh * HDIM * HDIM;
    for (int e = threadIdx.x; e < HDIM * HDIM; e += 256) {
        float s = 0.f;
        #pragma unroll
        for (int c = 0; c < 8; c++) s += base[c * HDIM * HDIM + e];
        out[e] = s * inv;
    }
}

// ---------------- attn_out = Q @ S ; write hi/lo bf16 split ----------------
__global__ __launch_bounds__(256) void qs_kernel(
    const float* __restrict__ q, const float* __restrict__ S,
    __nv_bfloat16* __restrict__ ah, __nv_bfloat16* __restrict__ al)
{
    int bh = blockIdx.y;
    int b = bh >> 4, h = bh & 15;
    int row0 = blockIdx.x * 64;

    __shared__ float Ss[HDIM][HDIM];
    __shared__ float qsm[64][HDIM + 1];

    const float* qb = q + (size_t)b * NTOK * FEATS + h * HDIM;
    const float* Sb = S + (size_t)bh * HDIM * HDIM;

    int tid = threadIdx.x;
    #pragma unroll
    for (int i = tid; i < 64 * 64; i += 256) {
        int r = i >> 6, cc = i & 63;
        Ss[r][cc] = Sb[i];
        qsm[r][cc] = qb[(size_t)(row0 + r) * FEATS + cc];
    }
    __syncthreads();

    int c  = tid & 63;
    int r0 = tid >> 6;
    #pragma unroll
    for (int i = 0; i < 16; i++) {
        int r = i * 4 + r0;
        float acc = 0.f;
        #pragma unroll
        for (int pp = 0; pp < HDIM; pp++)
            acc = fmaf(qsm[r][pp], Ss[pp][c], acc);
        size_t off = (size_t)(b * NTOK + row0 + r) * FEATS + h * HDIM + c;
        __nv_bfloat16 hh, ll;
        split2(acc, hh, ll);
        ah[off] = hh;
        al[off] = ll;
    }
}

// ---------------- launch ----------------
extern "C" void kernel_launch(void* const* d_in, const int* in_sizes, int n_in,
                              void* d_out, int out_size)
{
    const float* x  = (const float*)d_in[0];
    const float* Wq = (const float*)d_in[1];
    const float* bq = (const float*)d_in[2];
    const float* Wk = (const float*)d_in[3];
    const float* bk = (const float*)d_in[4];
    const float* Wv = (const float*)d_in[5];
    const float* bv = (const float*)d_in[6];
    const float* Wo = (const float*)d_in[7];
    const float* bo = (const float*)d_in[8];
    const float* m  = (const float*)d_in[9];
    float* out = (float*)d_out;

    float *q, *k, *v, *S, *Sp;
    __nv_bfloat16 *xh, *xl, *ah, *al, *wh, *wl;
    cudaGetSymbolAddress((void**)&q, g_q);
    cudaGetSymbolAddress((void**)&k, g_k);
    cudaGetSymbolAddress((void**)&v, g_v);
    cudaGetSymbolAddress((void**)&S, g_S);
    cudaGetSymbolAddress((void**)&Sp, g_Sp);
    cudaGetSymbolAddress((void**)&xh, g_xh);
    cudaGetSymbolAddress((void**)&xl, g_xl);
    cudaGetSymbolAddress((void**)&ah, g_ah);
    cudaGetSymbolAddress((void**)&al, g_al);
    cudaGetSymbolAddress((void**)&wh, g_wh);
    cudaGetSymbolAddress((void**)&wl, g_wl);

    static bool attr_done = false;
    cudaFuncSetAttribute(gemm_split3_kernel,
                         cudaFuncAttributeMaxDynamicSharedMemorySize,
                         NSTAGE * STG_BYTES);
    (void)attr_done;

    const size_t WSZ = (size_t)KDIM * NDIM;

    // splits
    split_kernel<<<MROWS * FEATS / 4 / 256, 256>>>(x, xh, xl, MROWS * FEATS / 4);
    split_kernel<<<WSZ / 4 / 256, 256>>>(Wq, wh + 0 * WSZ, wl + 0 * WSZ, WSZ / 4);
    split_kernel<<<WSZ / 4 / 256, 256>>>(Wk, wh + 1 * WSZ, wl + 1 * WSZ, WSZ / 4);
    split_kernel<<<WSZ / 4 / 256, 256>>>(Wv, wh + 2 * WSZ, wl + 2 * WSZ, WSZ / 4);
    split_kernel<<<WSZ / 4 / 256, 256>>>(Wo, wh + 3 * WSZ, wl + 3 * WSZ, WSZ / 4);

    dim3 gemm_grid(NDIM / BN_, MROWS / BM);   // (8, 64)
    size_t smem = NSTAGE * STG_BYTES;
    gemm_split3_kernel<<<gemm_grid, 256, smem>>>(xh, xl, wh + 0 * WSZ, wl + 0 * WSZ, bq, q);
    gemm_split3_kernel<<<gemm_grid, 256, smem>>>(xh, xl, wh + 1 * WSZ, wl + 1 * WSZ, bk, k);
    gemm_split3_kernel<<<gemm_grid, 256, smem>>>(xh, xl, wh + 2 * WSZ, wl + 2 * WSZ, bv, v);

    int nrows = MROWS * NHEAD;
    l2norm_kernel<<<nrows / 8, 256>>>(q, nrows);
    l2norm_kernel<<<nrows / 8, 256>>>(k, nrows);

    ktv_partial_kernel<<<BATCH * NHEAD * 8, 256>>>(k, v, Sp);
    ktv_reduce_kernel<<<BATCH * NHEAD, 256>>>(Sp, m, S);

    dim3 qs_grid(NTOK / 64, BATCH * NHEAD);
    qs_kernel<<<qs_grid, 256>>>(q, S, ah, al);

    gemm_split3_kernel<<<gemm_grid, 256, smem>>>(ah, al, wh + 3 * WSZ, wl + 3 * WSZ, bo, out);
}